// round 2
// baseline (speedup 1.0000x reference)
#include <cuda_runtime.h>

// Problem constants
#define B_   8
#define N_   1024
#define D_   512
#define C_   1024
#define Q_   8
#define M_   (B_ * N_)      // 8192 rows
#define D4_  (D_ / 4)       // 128 float4 per row

// GEMM tile config
#define BM 64
#define BN 128
#define BK 32

// Output layout (all float32): [quantized_out M*D][indices M*Q][losses Q]
#define OUT_IDX_OFF  ((size_t)M_ * D_)
#define OUT_LOSS_OFF ((size_t)M_ * D_ + (size_t)M_ * Q_)

// Scratch (allocation-free: __device__ globals)
__device__ float g_residual[M_ * D_];   // 16.8 MB
__device__ float g_e2[Q_ * C_];
__device__ float g_loss[Q_];

// ---------------------------------------------------------------------------
// init: residual = x, zero loss accumulators
// ---------------------------------------------------------------------------
__global__ void init_kernel(const float4* __restrict__ x) {
    const int n4 = M_ * D_ / 4;
    float4* r4 = (float4*)g_residual;
    for (int i = blockIdx.x * blockDim.x + threadIdx.x; i < n4;
         i += gridDim.x * blockDim.x)
        r4[i] = x[i];
    if (blockIdx.x == 0 && threadIdx.x < Q_) g_loss[threadIdx.x] = 0.f;
}

// ---------------------------------------------------------------------------
// e2: ||codebook[q][c]||^2 for all 8 codebooks (one warp per row)
// ---------------------------------------------------------------------------
__global__ void e2_kernel(const float* __restrict__ cbs) {
    const int warp = (blockIdx.x * blockDim.x + threadIdx.x) >> 5;
    const int lane = threadIdx.x & 31;
    if (warp >= Q_ * C_) return;
    const float* row = cbs + (size_t)warp * D_;
    float s = 0.f;
#pragma unroll
    for (int i = 0; i < D_ / 32; i++) {
        float v = row[lane + 32 * i];
        s = fmaf(v, v, s);
    }
#pragma unroll
    for (int o = 16; o > 0; o >>= 1) s += __shfl_xor_sync(0xffffffffu, s, o);
    if (lane == 0) g_e2[warp] = s;
}

// ---------------------------------------------------------------------------
// Fused layer: tiled GEMM (residual . codebook^T) -> running argmin per row ->
// gather winner, update residual in place, accumulate loss, emit indices.
// Grid: M_/BM = 128 blocks x 256 threads.
// ---------------------------------------------------------------------------
__global__ __launch_bounds__(256) void vq_layer_kernel(
    const float* __restrict__ cb,     // this layer's codebook [C_][D_]
    float* __restrict__ idx_out,      // d_out + OUT_IDX_OFF (or null)
    int q)
{
    __shared__ float As[BK][BM + 1];   // +1 pad: conflict-free transposed STS/LDS
    __shared__ float Bs[BK][BN + 1];
    __shared__ float e2s[C_];
    __shared__ float redv[BM][16];
    __shared__ int   redi[BM][16];
    __shared__ int   sidx[BM];
    __shared__ float sred[256];

    const int t  = threadIdx.x;
    const int tm = t & 15;     // row group: rows tm + 16*r
    const int tn = t >> 4;     // col group: cols tn + 16*s
    const int bm0 = blockIdx.x * BM;

    const float* e2 = g_e2 + q * C_;
    for (int i = t; i < C_; i += 256) e2s[i] = e2[i];

    float best[4];
    int   bidx[4];
#pragma unroll
    for (int r = 0; r < 4; r++) { best[r] = 3.4e38f; bidx[r] = 0; }

    float acc[4][8];
#pragma unroll
    for (int r = 0; r < 4; r++)
#pragma unroll
        for (int s = 0; s < 8; s++) acc[r][s] = 0.f;

    float ra[8], rb[16];
    const float* Ag = g_residual + (size_t)bm0 * D_;

    for (int cc = 0; cc < C_ / BN; cc++) {
        const int c0 = cc * BN;
        const float* Bg = cb + (size_t)c0 * D_;

        // prefetch k-chunk 0 into registers
#pragma unroll
        for (int u = 0; u < 8; u++) {
            int i = t + 256 * u;
            ra[u] = Ag[(i >> 5) * D_ + (i & 31)];
        }
#pragma unroll
        for (int u = 0; u < 16; u++) {
            int i = t + 256 * u;
            rb[u] = Bg[(i >> 5) * D_ + (i & 31)];
        }

        for (int kt = 0; kt < D_ / BK; kt++) {
            __syncthreads();
            // transposed store (k-major) — pad makes this conflict-free
#pragma unroll
            for (int u = 0; u < 8; u++) {
                int i = t + 256 * u;
                As[i & 31][i >> 5] = ra[u];
            }
#pragma unroll
            for (int u = 0; u < 16; u++) {
                int i = t + 256 * u;
                Bs[i & 31][i >> 5] = rb[u];
            }
            __syncthreads();

            // prefetch next k-chunk while computing this one
            if (kt + 1 < D_ / BK) {
                const int k0 = (kt + 1) * BK;
#pragma unroll
                for (int u = 0; u < 8; u++) {
                    int i = t + 256 * u;
                    ra[u] = Ag[(i >> 5) * D_ + k0 + (i & 31)];
                }
#pragma unroll
                for (int u = 0; u < 16; u++) {
                    int i = t + 256 * u;
                    rb[u] = Bg[(i >> 5) * D_ + k0 + (i & 31)];
                }
            }

#pragma unroll
            for (int kk = 0; kk < BK; kk++) {
                float a[4], b[8];
#pragma unroll
                for (int r = 0; r < 4; r++) a[r] = As[kk][tm + 16 * r];
#pragma unroll
                for (int s = 0; s < 8; s++) b[s] = Bs[kk][tn + 16 * s];
#pragma unroll
                for (int r = 0; r < 4; r++)
#pragma unroll
                    for (int s = 0; s < 8; s++)
                        acc[r][s] = fmaf(a[r], b[s], acc[r][s]);
            }
        }

        // fold chunk into running min (ascending c + strict < => first-min)
#pragma unroll
        for (int s = 0; s < 8; s++) {
            int c = c0 + tn + 16 * s;
            float e = e2s[c];
#pragma unroll
            for (int r = 0; r < 4; r++) {
                float d = fmaf(-2.f, acc[r][s], e);
                if (d < best[r]) { best[r] = d; bidx[r] = c; }
                acc[r][s] = 0.f;
            }
        }
    }

    // cross-thread reduction: 16 col-groups share each row
#pragma unroll
    for (int r = 0; r < 4; r++) {
        redv[tm + 16 * r][tn] = best[r];
        redi[tm + 16 * r][tn] = bidx[r];
    }
    __syncthreads();
    if (t < BM) {
        float bv = redv[t][0];
        int   bi = redi[t][0];
#pragma unroll
        for (int j = 1; j < 16; j++) {
            float v = redv[t][j];
            int   i2 = redi[t][j];
            if (v < bv || (v == bv && i2 < bi)) { bv = v; bi = i2; }
        }
        sidx[t] = bi;
        if (idx_out)
            idx_out[(size_t)(bm0 + t) * Q_ + q] = (float)bi;
    }
    __syncthreads();

    // epilogue: residual -= codebook[idx]; loss += ||new residual||^2
    float4* R4 = (float4*)g_residual + (size_t)bm0 * D4_;
    const float4* C4 = (const float4*)cb;
    float sq = 0.f;
    for (int i = t; i < BM * D4_; i += 256) {
        int row = i >> 7;
        int j   = i & 127;
        int idx = sidx[row];
        float4 rv = R4[row * D4_ + j];
        float4 cv = C4[(size_t)idx * D4_ + j];
        rv.x -= cv.x; rv.y -= cv.y; rv.z -= cv.z; rv.w -= cv.w;
        R4[row * D4_ + j] = rv;
        sq = fmaf(rv.x, rv.x, sq);
        sq = fmaf(rv.y, rv.y, sq);
        sq = fmaf(rv.z, rv.z, sq);
        sq = fmaf(rv.w, rv.w, sq);
    }
    sred[t] = sq;
    __syncthreads();
    for (int o = 128; o > 0; o >>= 1) {
        if (t < o) sred[t] += sred[t + o];
        __syncthreads();
    }
    if (t == 0) atomicAdd(&g_loss[q], sred[0]);
}

// ---------------------------------------------------------------------------
// final: quantized_out = x - residual_final; write losses
// ---------------------------------------------------------------------------
__global__ void final_kernel(const float4* __restrict__ x,
                             float* __restrict__ out, int write_extra) {
    const int n4 = M_ * D_ / 4;
    float4* o4 = (float4*)out;
    const float4* r4 = (const float4*)g_residual;
    for (int i = blockIdx.x * blockDim.x + threadIdx.x; i < n4;
         i += gridDim.x * blockDim.x) {
        float4 xv = x[i], rv = r4[i];
        float4 ov;
        ov.x = xv.x - rv.x; ov.y = xv.y - rv.y;
        ov.z = xv.z - rv.z; ov.w = xv.w - rv.w;
        o4[i] = ov;
    }
    if (write_extra && blockIdx.x == 0 && threadIdx.x < Q_)
        out[OUT_LOSS_OFF + threadIdx.x] =
            g_loss[threadIdx.x] * (1.0f / ((float)M_ * (float)D_));
}

// ---------------------------------------------------------------------------
extern "C" void kernel_launch(void* const* d_in, const int* in_sizes, int n_in,
                              void* d_out, int out_size) {
    const float* x   = (const float*)d_in[0];
    const float* cbs = (const float*)d_in[1];
    float* out = (float*)d_out;

    const int full = (int)(OUT_LOSS_OFF + Q_);
    const int write_extra = (out_size >= full) ? 1 : 0;
    float* idx_out = write_extra ? out + OUT_IDX_OFF : nullptr;

    init_kernel<<<512, 256>>>((const float4*)x);
    e2_kernel<<<(Q_ * C_ * 32) / 256, 256>>>(cbs);
    for (int q = 0; q < Q_; q++)
        vq_layer_kernel<<<M_ / BM, 256>>>(cbs + (size_t)q * C_ * D_,
                                          idx_out, q);
    final_kernel<<<512, 256>>>((const float4*)x, out, write_extra);
}

// round 4
// speedup vs baseline: 1.2940x; 1.2940x over previous
#include <cuda_runtime.h>
#include <cuda_bf16.h>
#include <cstdint>

// ---------------------------------------------------------------------------
// Problem constants
// ---------------------------------------------------------------------------
#define B_   8
#define N_   1024
#define D_   512
#define C_   1024
#define Q_   8
#define M_   (B_ * N_)      // 8192 rows
#define D4_  (D_ / 4)

// Output layout (all float32): [quantized_out M*D][indices M*Q][losses Q]
#define OUT_IDX_OFF  ((size_t)M_ * D_)
#define OUT_LOSS_OFF ((size_t)M_ * D_ + (size_t)M_ * Q_)

// ---------------------------------------------------------------------------
// Scratch (__device__ globals — allocation-free)
// ---------------------------------------------------------------------------
__device__ float g_residual[M_ * D_];
__device__ __nv_bfloat16 gA0[M_ * D_];     // residual split hi
__device__ __nv_bfloat16 gA1[M_ * D_];     // mid
__device__ __nv_bfloat16 gA2[M_ * D_];     // lo
__device__ __nv_bfloat16 gB0[Q_ * C_ * D_];
__device__ __nv_bfloat16 gB1[Q_ * C_ * D_];
__device__ __nv_bfloat16 gB2[Q_ * C_ * D_];
__device__ float g_e2[Q_ * C_];
__device__ float g_loss[Q_];
__device__ unsigned long long g_argmin[M_];

// ---------------------------------------------------------------------------
// Arch-neutral PTX helpers (sm_80-level: cp.async / ldmatrix / mma.sync)
// ---------------------------------------------------------------------------
__device__ __forceinline__ uint32_t smem_to_u32(const void* p) {
    uint32_t a;
    asm("{ .reg .u64 t; cvta.to.shared.u64 t, %1; cvt.u32.u64 %0, t; }"
        : "=r"(a) : "l"(p));
    return a;
}
__device__ __forceinline__ void cp16(uint32_t dst, const void* src) {
    asm volatile("cp.async.cg.shared.global [%0], [%1], 16;"
                 :: "r"(dst), "l"(src));
}
#define CP_COMMIT() asm volatile("cp.async.commit_group;" ::: "memory")
#define CP_WAIT(n)  asm volatile("cp.async.wait_group %0;" :: "n"(n) : "memory")

__device__ __forceinline__ void ldm_x4(uint32_t* r, uint32_t addr) {
    asm volatile("ldmatrix.sync.aligned.m8n8.x4.shared.b16 {%0,%1,%2,%3}, [%4];"
                 : "=r"(r[0]), "=r"(r[1]), "=r"(r[2]), "=r"(r[3]) : "r"(addr));
}
__device__ __forceinline__ void mma16816(float* d, const uint32_t* a,
                                         uint32_t b0, uint32_t b1) {
    asm volatile(
        "mma.sync.aligned.m16n8k16.row.col.f32.bf16.bf16.f32 "
        "{%0,%1,%2,%3}, {%4,%5,%6,%7}, {%8,%9}, {%0,%1,%2,%3};"
        : "+f"(d[0]), "+f"(d[1]), "+f"(d[2]), "+f"(d[3])
        : "r"(a[0]), "r"(a[1]), "r"(a[2]), "r"(a[3]), "r"(b0), "r"(b1));
}

// ---------------------------------------------------------------------------
// bf16 triple split
// ---------------------------------------------------------------------------
__device__ __forceinline__ void split3(float x, __nv_bfloat16& h0,
                                       __nv_bfloat16& h1, __nv_bfloat16& h2) {
    h0 = __float2bfloat16(x);
    float r = x - __bfloat162float(h0);
    h1 = __float2bfloat16(r);
    r -= __bfloat162float(h1);
    h2 = __float2bfloat16(r);
}

// ---------------------------------------------------------------------------
// init: residual = x (+ splits), reset argmin, zero loss
// ---------------------------------------------------------------------------
__global__ void init_kernel(const float* __restrict__ x) {
    const int tid = blockIdx.x * blockDim.x + threadIdx.x;
    const int stride = gridDim.x * blockDim.x;
    for (int i = tid; i < M_ * D_; i += stride) {
        float v = x[i];
        g_residual[i] = v;
        __nv_bfloat16 h0, h1, h2;
        split3(v, h0, h1, h2);
        gA0[i] = h0; gA1[i] = h1; gA2[i] = h2;
    }
    for (int i = tid; i < M_; i += stride) g_argmin[i] = ~0ull;
    if (tid < Q_) g_loss[tid] = 0.f;
}

// ---------------------------------------------------------------------------
// prep: e2 + bf16 splits for all 8 codebooks (one warp per row)
// ---------------------------------------------------------------------------
__global__ void prep_kernel(const float* __restrict__ cbs) {
    const int w = (blockIdx.x * blockDim.x + threadIdx.x) >> 5;
    const int lane = threadIdx.x & 31;
    if (w >= Q_ * C_) return;
    const float* row = cbs + (size_t)w * D_;
    __nv_bfloat16* b0 = gB0 + (size_t)w * D_;
    __nv_bfloat16* b1 = gB1 + (size_t)w * D_;
    __nv_bfloat16* b2 = gB2 + (size_t)w * D_;
    float s = 0.f;
#pragma unroll
    for (int i = lane; i < D_; i += 32) {
        float v = row[i];
        s = fmaf(v, v, s);
        __nv_bfloat16 h0, h1, h2;
        split3(v, h0, h1, h2);
        b0[i] = h0; b1[i] = h1; b2[i] = h2;
    }
#pragma unroll
    for (int o = 16; o > 0; o >>= 1) s += __shfl_xor_sync(0xffffffffu, s, o);
    if (lane == 0) g_e2[w] = s;
}

// ---------------------------------------------------------------------------
// GEMM + argmin via mma.sync bf16 (6-term split => expanded K' = 3072)
// CTA tile 128x128, 8 warps @ 64x32, k-chunks of 32, cp.async double buffer.
// Grid: (M/128=64, C/128=8). Smem rows padded to 80B (ldmatrix conflict-free).
// ---------------------------------------------------------------------------
#define ROWB   80              // bytes per smem row (32 bf16 + 8 pad)
#define ABUF   10240           // 128 * 80
#define NCHUNK 96              // 6 segments * 16 chunks of k=32

__global__ void __launch_bounds__(256, 2) gemm_argmin_kernel(int q) {
    __shared__ __align__(128) char sA[2 * ABUF];
    __shared__ __align__(128) char sB[2 * ABUF];
    __shared__ float e2s[128];

    const int t = threadIdx.x;
    const int lane = t & 31, wid = t >> 5;
    const int warp_m = (wid >> 2) * 64;     // 0 or 64
    const int warp_n = (wid & 3) * 32;      // 0..96
    const int bm0 = blockIdx.x * 128;
    const int c0  = blockIdx.y * 128;

    const __nv_bfloat16* Bq0 = gB0 + (size_t)q * C_ * D_;
    const __nv_bfloat16* Bq1 = gB1 + (size_t)q * C_ * D_;
    const __nv_bfloat16* Bq2 = gB2 + (size_t)q * C_ * D_;

    if (t < 128) e2s[t] = g_e2[q * C_ + c0 + t];

    const uint32_t sAu = smem_to_u32(sA);
    const uint32_t sBu = smem_to_u32(sB);

    // loader mapping: thread -> (row, 2 x 16B granules) for A and same for B
    const int lrow = t >> 1;
    const int lgr  = (t & 1) * 2;           // granule pair: bf16 offset lgr*8

    // ldmatrix lane offsets (bytes, k added later)
    uint32_t a_off[4];
#pragma unroll
    for (int ma = 0; ma < 4; ma++)
        a_off[ma] = (uint32_t)((warp_m + ma * 16 + (lane & 15)) * ROWB +
                               (lane >> 4) * 16);
    uint32_t b_off[2];
#pragma unroll
    for (int p = 0; p < 2; p++)
        b_off[p] = (uint32_t)((warp_n + p * 16 + ((lane >> 4) << 3) + (lane & 7)) * ROWB +
                              ((lane >> 3) & 1) * 16);

    float acc[4][4][4];
#pragma unroll
    for (int i = 0; i < 4; i++)
#pragma unroll
        for (int j = 0; j < 4; j++)
#pragma unroll
            for (int e = 0; e < 4; e++) acc[i][j][e] = 0.f;

    // segment tables: term s pairs (A split, B split)
    // s: 0:A0B0 1:A0B1 2:A1B0 3:A0B2 4:A1B1 5:A2B0
    auto pick = [&](int seg, const __nv_bfloat16*& pa, const __nv_bfloat16*& pb) {
        switch (seg) {
            case 0: pa = gA0; pb = Bq0; break;
            case 1: pa = gA0; pb = Bq1; break;
            case 2: pa = gA1; pb = Bq0; break;
            case 3: pa = gA0; pb = Bq2; break;
            case 4: pa = gA1; pb = Bq1; break;
            default: pa = gA2; pb = Bq0; break;
        }
    };
    auto issue_loads = [&](int cc) {
        const __nv_bfloat16 *pa, *pb;
        pick(cc >> 4, pa, pb);
        const int kk0 = (cc & 15) * 32;
        const uint32_t buf = (cc & 1) * ABUF;
        const __nv_bfloat16* ga = pa + (size_t)(bm0 + lrow) * D_ + kk0 + lgr * 8;
        uint32_t da = sAu + buf + lrow * ROWB + lgr * 16;
        cp16(da, ga); cp16(da + 16, ga + 8);
        const __nv_bfloat16* gb = pb + (size_t)(c0 + lrow) * D_ + kk0 + lgr * 8;
        uint32_t db = sBu + buf + lrow * ROWB + lgr * 16;
        cp16(db, gb); cp16(db + 16, gb + 8);
        CP_COMMIT();
    };

    issue_loads(0);

    for (int cc = 0; cc < NCHUNK; cc++) {
        if (cc + 1 < NCHUNK) { issue_loads(cc + 1); CP_WAIT(1); }
        else                 { CP_WAIT(0); }
        __syncthreads();

        const uint32_t aBase = sAu + (cc & 1) * ABUF;
        const uint32_t bBase = sBu + (cc & 1) * ABUF;
#pragma unroll
        for (int k = 0; k < 32; k += 16) {
            uint32_t afr[4][4], bfr[2][4];
#pragma unroll
            for (int ma = 0; ma < 4; ma++)
                ldm_x4(afr[ma], aBase + a_off[ma] + k * 2);
#pragma unroll
            for (int p = 0; p < 2; p++)
                ldm_x4(bfr[p], bBase + b_off[p] + k * 2);
#pragma unroll
            for (int ma = 0; ma < 4; ma++) {
#pragma unroll
                for (int nb = 0; nb < 4; nb++) {
                    const uint32_t* bp = bfr[nb >> 1];
                    mma16816(acc[ma][nb], afr[ma],
                             bp[(nb & 1) * 2], bp[(nb & 1) * 2 + 1]);
                }
            }
        }
        __syncthreads();
    }

    // epilogue: key = e2 - 2*dot, per-row argmin (first-min via idx tiebreak)
    const int g = lane >> 2, tg = lane & 3;
#pragma unroll
    for (int ma = 0; ma < 4; ma++) {
#pragma unroll
        for (int half = 0; half < 2; half++) {
            float bv = 3.4e38f;
            int bi = 0;
#pragma unroll
            for (int nb = 0; nb < 4; nb++) {
#pragma unroll
                for (int e2i = 0; e2i < 2; e2i++) {
                    const int cloc = warp_n + nb * 8 + tg * 2 + e2i;
                    float key = fmaf(-2.f, acc[ma][nb][half * 2 + e2i], e2s[cloc]);
                    if (key < bv) { bv = key; bi = c0 + cloc; }
                }
            }
            uint32_t u = __float_as_uint(bv);
            u = (u & 0x80000000u) ? ~u : (u | 0x80000000u);
            unsigned long long pk = ((unsigned long long)u << 32) | (unsigned)bi;
#pragma unroll
            for (int o = 1; o <= 2; o <<= 1) {
                unsigned long long other = __shfl_xor_sync(0xffffffffu, pk, o);
                if (other < pk) pk = other;
            }
            if (tg == 0)
                atomicMin(&g_argmin[bm0 + warp_m + ma * 16 + half * 8 + g], pk);
        }
    }
}

// ---------------------------------------------------------------------------
// update: gather winner, residual -= cb[idx], loss, re-split, reset argmin
// ---------------------------------------------------------------------------
__global__ void __launch_bounds__(256) update_kernel(
    const float* __restrict__ cb, float* __restrict__ idx_out, int q, int last) {
    const int row0 = blockIdx.x * 32;
    const int t = threadIdx.x;
    __shared__ int sidx[32];
    __shared__ float sred[256];

    if (t < 32) {
        unsigned long long v = g_argmin[row0 + t];
        int c = (int)(v & 0xFFFFFFFFull);
        sidx[t] = c;
        g_argmin[row0 + t] = ~0ull;
        if (idx_out) idx_out[(size_t)(row0 + t) * Q_ + q] = (float)c;
    }
    __syncthreads();

    float sq = 0.f;
    for (int i = t; i < 32 * D4_; i += 256) {
        const int row = i >> 7, j = i & 127;
        const int idx = sidx[row];
        const size_t rg = (size_t)(row0 + row) * D4_ + j;
        float4 rv = ((float4*)g_residual)[rg];
        const float4 cv = ((const float4*)cb)[(size_t)idx * D4_ + j];
        rv.x -= cv.x; rv.y -= cv.y; rv.z -= cv.z; rv.w -= cv.w;
        ((float4*)g_residual)[rg] = rv;
        sq = fmaf(rv.x, rv.x, sq); sq = fmaf(rv.y, rv.y, sq);
        sq = fmaf(rv.z, rv.z, sq); sq = fmaf(rv.w, rv.w, sq);
        if (!last) {
            const size_t e = (size_t)(row0 + row) * D_ + (size_t)j * 4;
            float vals[4] = {rv.x, rv.y, rv.z, rv.w};
            uint32_t p0[2], p1[2], p2[2];
#pragma unroll
            for (int hp = 0; hp < 2; hp++) {
                __nv_bfloat16 a0, a1, a2, b0h, b1h, b2h;
                split3(vals[2 * hp], a0, a1, a2);
                split3(vals[2 * hp + 1], b0h, b1h, b2h);
                p0[hp] = (uint32_t)__bfloat16_as_ushort(a0) |
                         ((uint32_t)__bfloat16_as_ushort(b0h) << 16);
                p1[hp] = (uint32_t)__bfloat16_as_ushort(a1) |
                         ((uint32_t)__bfloat16_as_ushort(b1h) << 16);
                p2[hp] = (uint32_t)__bfloat16_as_ushort(a2) |
                         ((uint32_t)__bfloat16_as_ushort(b2h) << 16);
            }
            *(uint2*)&gA0[e] = make_uint2(p0[0], p0[1]);
            *(uint2*)&gA1[e] = make_uint2(p1[0], p1[1]);
            *(uint2*)&gA2[e] = make_uint2(p2[0], p2[1]);
        }
    }
    sred[t] = sq;
    __syncthreads();
    for (int o = 128; o > 0; o >>= 1) {
        if (t < o) sred[t] += sred[t + o];
        __syncthreads();
    }
    if (t == 0) atomicAdd(&g_loss[q], sred[0]);
}

// ---------------------------------------------------------------------------
// final: quantized_out = x - residual_final; write losses
// ---------------------------------------------------------------------------
__global__ void final_kernel(const float4* __restrict__ x,
                             float* __restrict__ out, int write_extra) {
    const int n4 = M_ * D_ / 4;
    float4* o4 = (float4*)out;
    const float4* r4 = (const float4*)g_residual;
    for (int i = blockIdx.x * blockDim.x + threadIdx.x; i < n4;
         i += gridDim.x * blockDim.x) {
        float4 xv = x[i], rv = r4[i];
        float4 ov;
        ov.x = xv.x - rv.x; ov.y = xv.y - rv.y;
        ov.z = xv.z - rv.z; ov.w = xv.w - rv.w;
        o4[i] = ov;
    }
    if (write_extra && blockIdx.x == 0 && threadIdx.x < Q_)
        out[OUT_LOSS_OFF + threadIdx.x] =
            g_loss[threadIdx.x] * (1.0f / ((float)M_ * (float)D_));
}

// ---------------------------------------------------------------------------
extern "C" void kernel_launch(void* const* d_in, const int* in_sizes, int n_in,
                              void* d_out, int out_size) {
    const float* x   = (const float*)d_in[0];
    const float* cbs = (const float*)d_in[1];
    float* out = (float*)d_out;

    const int full = (int)(OUT_LOSS_OFF + Q_);
    const int write_extra = (out_size >= full) ? 1 : 0;
    float* idx_out = write_extra ? out + OUT_IDX_OFF : nullptr;

    init_kernel<<<1024, 256>>>(x);
    prep_kernel<<<(Q_ * C_ * 32) / 256, 256>>>(cbs);
    for (int q = 0; q < Q_; q++) {
        gemm_argmin_kernel<<<dim3(64, 8), 256>>>(q);
        update_kernel<<<256, 256>>>(cbs + (size_t)q * C_ * D_, idx_out, q,
                                    q == Q_ - 1);
    }
    final_kernel<<<512, 256>>>((const float4*)x, out, write_extra);
}

// round 5
// speedup vs baseline: 2.4642x; 1.9044x over previous
#include <cuda_runtime.h>
#include <cuda_fp16.h>
#include <cstdint>

// ---------------------------------------------------------------------------
// Problem constants
// ---------------------------------------------------------------------------
#define B_   8
#define N_   1024
#define D_   512
#define C_   1024
#define Q_   8
#define M_   (B_ * N_)      // 8192 rows
#define D4_  (D_ / 4)

// Output layout (all float32): [quantized_out M*D][indices M*Q][losses Q]
#define OUT_IDX_OFF  ((size_t)M_ * D_)
#define OUT_LOSS_OFF ((size_t)M_ * D_ + (size_t)M_ * Q_)

// ---------------------------------------------------------------------------
// Scratch (__device__ globals — allocation-free)
// ---------------------------------------------------------------------------
__device__ float g_residual[M_ * D_];
__device__ __half gA0[M_ * D_];            // residual split hi (fp16)
__device__ __half gA1[M_ * D_];            // residual split lo
__device__ __half gB0[Q_ * C_ * D_];       // codebook split hi
__device__ __half gB1[Q_ * C_ * D_];       // codebook split lo
__device__ float g_e2[Q_ * C_];
__device__ float g_loss[Q_];
__device__ unsigned long long g_argmin[M_];

// ---------------------------------------------------------------------------
// Arch-neutral PTX helpers (sm_80-level: cp.async / ldmatrix / mma.sync)
// ---------------------------------------------------------------------------
__device__ __forceinline__ uint32_t smem_to_u32(const void* p) {
    uint32_t a;
    asm("{ .reg .u64 t; cvta.to.shared.u64 t, %1; cvt.u32.u64 %0, t; }"
        : "=r"(a) : "l"(p));
    return a;
}
__device__ __forceinline__ void cp16(uint32_t dst, const void* src) {
    asm volatile("cp.async.cg.shared.global [%0], [%1], 16;"
                 :: "r"(dst), "l"(src));
}
#define CP_COMMIT() asm volatile("cp.async.commit_group;" ::: "memory")
#define CP_WAIT(n)  asm volatile("cp.async.wait_group %0;" :: "n"(n) : "memory")

__device__ __forceinline__ void ldm_x4(uint32_t* r, uint32_t addr) {
    asm volatile("ldmatrix.sync.aligned.m8n8.x4.shared.b16 {%0,%1,%2,%3}, [%4];"
                 : "=r"(r[0]), "=r"(r[1]), "=r"(r[2]), "=r"(r[3]) : "r"(addr));
}
__device__ __forceinline__ void mma16816(float* d, const uint32_t* a,
                                         uint32_t b0, uint32_t b1) {
    asm volatile(
        "mma.sync.aligned.m16n8k16.row.col.f32.f16.f16.f32 "
        "{%0,%1,%2,%3}, {%4,%5,%6,%7}, {%8,%9}, {%0,%1,%2,%3};"
        : "+f"(d[0]), "+f"(d[1]), "+f"(d[2]), "+f"(d[3])
        : "r"(a[0]), "r"(a[1]), "r"(a[2]), "r"(a[3]), "r"(b0), "r"(b1));
}

// ---------------------------------------------------------------------------
// fp16 double split: x = h0 + h1 + O(2^-22 x)
// ---------------------------------------------------------------------------
__device__ __forceinline__ void split2(float x, __half& h0, __half& h1) {
    h0 = __float2half_rn(x);
    h1 = __float2half_rn(x - __half2float(h0));
}

// ---------------------------------------------------------------------------
// init: residual = x (+ splits), reset argmin, zero loss
// ---------------------------------------------------------------------------
__global__ void init_kernel(const float* __restrict__ x) {
    const int tid = blockIdx.x * blockDim.x + threadIdx.x;
    const int stride = gridDim.x * blockDim.x;
    for (int i = tid; i < M_ * D_; i += stride) {
        float v = x[i];
        g_residual[i] = v;
        __half h0, h1;
        split2(v, h0, h1);
        gA0[i] = h0; gA1[i] = h1;
    }
    for (int i = tid; i < M_; i += stride) g_argmin[i] = ~0ull;
    if (tid < Q_) g_loss[tid] = 0.f;
}

// ---------------------------------------------------------------------------
// prep: e2 + fp16 splits for all 8 codebooks (one warp per row)
// ---------------------------------------------------------------------------
__global__ void prep_kernel(const float* __restrict__ cbs) {
    const int w = (blockIdx.x * blockDim.x + threadIdx.x) >> 5;
    const int lane = threadIdx.x & 31;
    if (w >= Q_ * C_) return;
    const float* row = cbs + (size_t)w * D_;
    __half* b0 = gB0 + (size_t)w * D_;
    __half* b1 = gB1 + (size_t)w * D_;
    float s = 0.f;
#pragma unroll
    for (int i = lane; i < D_; i += 32) {
        float v = row[i];
        s = fmaf(v, v, s);
        __half h0, h1;
        split2(v, h0, h1);
        b0[i] = h0; b1[i] = h1;
    }
#pragma unroll
    for (int o = 16; o > 0; o >>= 1) s += __shfl_xor_sync(0xffffffffu, s, o);
    if (lane == 0) g_e2[w] = s;
}

// ---------------------------------------------------------------------------
// GEMM + argmin via mma.sync fp16 (3-term split => expanded K' = 1536)
// CTA tile 128x128, 8 warps @ 64x32, k-chunks of 32, cp.async double buffer.
// Grid: (M/128=64, C/128=8). Smem rows padded to 80B (ldmatrix conflict-free).
// ---------------------------------------------------------------------------
#define ROWB   80              // bytes per smem row (32 fp16 + 8 pad)
#define ABUF   10240           // 128 * 80
#define NCHUNK 48              // 3 segments * 16 chunks of k=32

__global__ void __launch_bounds__(256, 2) gemm_argmin_kernel(int q) {
    __shared__ __align__(128) char sA[2 * ABUF];
    __shared__ __align__(128) char sB[2 * ABUF];
    __shared__ float e2s[128];

    const int t = threadIdx.x;
    const int lane = t & 31, wid = t >> 5;
    const int warp_m = (wid >> 2) * 64;     // 0 or 64
    const int warp_n = (wid & 3) * 32;      // 0..96
    const int bm0 = blockIdx.x * 128;
    const int c0  = blockIdx.y * 128;

    const __half* Bq0 = gB0 + (size_t)q * C_ * D_;
    const __half* Bq1 = gB1 + (size_t)q * C_ * D_;

    if (t < 128) e2s[t] = g_e2[q * C_ + c0 + t];

    const uint32_t sAu = smem_to_u32(sA);
    const uint32_t sBu = smem_to_u32(sB);

    // loader mapping: thread -> (row, 2 x 16B granules)
    const int lrow = t >> 1;
    const int lgr  = (t & 1) * 2;

    uint32_t a_off[4];
#pragma unroll
    for (int ma = 0; ma < 4; ma++)
        a_off[ma] = (uint32_t)((warp_m + ma * 16 + (lane & 15)) * ROWB +
                               (lane >> 4) * 16);
    uint32_t b_off[2];
#pragma unroll
    for (int p = 0; p < 2; p++)
        b_off[p] = (uint32_t)((warp_n + p * 16 + ((lane >> 4) << 3) + (lane & 7)) * ROWB +
                              ((lane >> 3) & 1) * 16);

    float acc[4][4][4];
#pragma unroll
    for (int i = 0; i < 4; i++)
#pragma unroll
        for (int j = 0; j < 4; j++)
#pragma unroll
            for (int e = 0; e < 4; e++) acc[i][j][e] = 0.f;

    // segments: 0:A0B0  1:A0B1  2:A1B0
    auto pick = [&](int seg, const __half*& pa, const __half*& pb) {
        switch (seg) {
            case 0: pa = gA0; pb = Bq0; break;
            case 1: pa = gA0; pb = Bq1; break;
            default: pa = gA1; pb = Bq0; break;
        }
    };
    auto issue_loads = [&](int cc) {
        const __half *pa, *pb;
        pick(cc >> 4, pa, pb);
        const int kk0 = (cc & 15) * 32;
        const uint32_t buf = (cc & 1) * ABUF;
        const __half* ga = pa + (size_t)(bm0 + lrow) * D_ + kk0 + lgr * 8;
        uint32_t da = sAu + buf + lrow * ROWB + lgr * 16;
        cp16(da, ga); cp16(da + 16, ga + 8);
        const __half* gb = pb + (size_t)(c0 + lrow) * D_ + kk0 + lgr * 8;
        uint32_t db = sBu + buf + lrow * ROWB + lgr * 16;
        cp16(db, gb); cp16(db + 16, gb + 8);
        CP_COMMIT();
    };

    issue_loads(0);

    for (int cc = 0; cc < NCHUNK; cc++) {
        if (cc + 1 < NCHUNK) { issue_loads(cc + 1); CP_WAIT(1); }
        else                 { CP_WAIT(0); }
        __syncthreads();

        const uint32_t aBase = sAu + (cc & 1) * ABUF;
        const uint32_t bBase = sBu + (cc & 1) * ABUF;
#pragma unroll
        for (int k = 0; k < 32; k += 16) {
            uint32_t afr[4][4], bfr[2][4];
#pragma unroll
            for (int ma = 0; ma < 4; ma++)
                ldm_x4(afr[ma], aBase + a_off[ma] + k * 2);
#pragma unroll
            for (int p = 0; p < 2; p++)
                ldm_x4(bfr[p], bBase + b_off[p] + k * 2);
#pragma unroll
            for (int ma = 0; ma < 4; ma++) {
#pragma unroll
                for (int nb = 0; nb < 4; nb++) {
                    const uint32_t* bp = bfr[nb >> 1];
                    mma16816(acc[ma][nb], afr[ma],
                             bp[(nb & 1) * 2], bp[(nb & 1) * 2 + 1]);
                }
            }
        }
        __syncthreads();
    }

    // epilogue: key = e2 - 2*dot, per-row argmin (first-min via idx tiebreak)
    const int g = lane >> 2, tg = lane & 3;
#pragma unroll
    for (int ma = 0; ma < 4; ma++) {
#pragma unroll
        for (int half = 0; half < 2; half++) {
            float bv = 3.4e38f;
            int bi = 0;
#pragma unroll
            for (int nb = 0; nb < 4; nb++) {
#pragma unroll
                for (int e2i = 0; e2i < 2; e2i++) {
                    const int cloc = warp_n + nb * 8 + tg * 2 + e2i;
                    float key = fmaf(-2.f, acc[ma][nb][half * 2 + e2i], e2s[cloc]);
                    if (key < bv) { bv = key; bi = c0 + cloc; }
                }
            }
            uint32_t u = __float_as_uint(bv);
            u = (u & 0x80000000u) ? ~u : (u | 0x80000000u);
            unsigned long long pk = ((unsigned long long)u << 32) | (unsigned)bi;
#pragma unroll
            for (int o = 1; o <= 2; o <<= 1) {
                unsigned long long other = __shfl_xor_sync(0xffffffffu, pk, o);
                if (other < pk) pk = other;
            }
            if (tg == 0)
                atomicMin(&g_argmin[bm0 + warp_m + ma * 16 + half * 8 + g], pk);
        }
    }
}

// ---------------------------------------------------------------------------
// update: gather winner, residual -= cb[idx], loss, re-split, reset argmin
// ---------------------------------------------------------------------------
__global__ void __launch_bounds__(256) update_kernel(
    const float* __restrict__ cb, float* __restrict__ idx_out, int q, int last) {
    const int row0 = blockIdx.x * 32;
    const int t = threadIdx.x;
    __shared__ int sidx[32];
    __shared__ float sred[256];

    if (t < 32) {
        unsigned long long v = g_argmin[row0 + t];
        int c = (int)(v & 0xFFFFFFFFull);
        sidx[t] = c;
        g_argmin[row0 + t] = ~0ull;
        if (idx_out) idx_out[(size_t)(row0 + t) * Q_ + q] = (float)c;
    }
    __syncthreads();

    float sq = 0.f;
    for (int i = t; i < 32 * D4_; i += 256) {
        const int row = i >> 7, j = i & 127;
        const int idx = sidx[row];
        const size_t rg = (size_t)(row0 + row) * D4_ + j;
        float4 rv = ((float4*)g_residual)[rg];
        const float4 cv = ((const float4*)cb)[(size_t)idx * D4_ + j];
        rv.x -= cv.x; rv.y -= cv.y; rv.z -= cv.z; rv.w -= cv.w;
        ((float4*)g_residual)[rg] = rv;
        sq = fmaf(rv.x, rv.x, sq); sq = fmaf(rv.y, rv.y, sq);
        sq = fmaf(rv.z, rv.z, sq); sq = fmaf(rv.w, rv.w, sq);
        if (!last) {
            const size_t e = (size_t)(row0 + row) * D_ + (size_t)j * 4;
            float vals[4] = {rv.x, rv.y, rv.z, rv.w};
            uint32_t p0[2], p1[2];
#pragma unroll
            for (int hp = 0; hp < 2; hp++) {
                __half a0, a1, b0h, b1h;
                split2(vals[2 * hp], a0, a1);
                split2(vals[2 * hp + 1], b0h, b1h);
                p0[hp] = (uint32_t)__half_as_ushort(a0) |
                         ((uint32_t)__half_as_ushort(b0h) << 16);
                p1[hp] = (uint32_t)__half_as_ushort(a1) |
                         ((uint32_t)__half_as_ushort(b1h) << 16);
            }
            *(uint2*)&gA0[e] = make_uint2(p0[0], p0[1]);
            *(uint2*)&gA1[e] = make_uint2(p1[0], p1[1]);
        }
    }
    sred[t] = sq;
    __syncthreads();
    for (int o = 128; o > 0; o >>= 1) {
        if (t < o) sred[t] += sred[t + o];
        __syncthreads();
    }
    if (t == 0) atomicAdd(&g_loss[q], sred[0]);
}

// ---------------------------------------------------------------------------
// final: quantized_out = x - residual_final; write losses
// ---------------------------------------------------------------------------
__global__ void final_kernel(const float4* __restrict__ x,
                             float* __restrict__ out, int write_extra) {
    const int n4 = M_ * D_ / 4;
    float4* o4 = (float4*)out;
    const float4* r4 = (const float4*)g_residual;
    for (int i = blockIdx.x * blockDim.x + threadIdx.x; i < n4;
         i += gridDim.x * blockDim.x) {
        float4 xv = x[i], rv = r4[i];
        float4 ov;
        ov.x = xv.x - rv.x; ov.y = xv.y - rv.y;
        ov.z = xv.z - rv.z; ov.w = xv.w - rv.w;
        o4[i] = ov;
    }
    if (write_extra && blockIdx.x == 0 && threadIdx.x < Q_)
        out[OUT_LOSS_OFF + threadIdx.x] =
            g_loss[threadIdx.x] * (1.0f / ((float)M_ * (float)D_));
}

// ---------------------------------------------------------------------------
extern "C" void kernel_launch(void* const* d_in, const int* in_sizes, int n_in,
                              void* d_out, int out_size) {
    const float* x   = (const float*)d_in[0];
    const float* cbs = (const float*)d_in[1];
    float* out = (float*)d_out;

    const int full = (int)(OUT_LOSS_OFF + Q_);
    const int write_extra = (out_size >= full) ? 1 : 0;
    float* idx_out = write_extra ? out + OUT_IDX_OFF : nullptr;

    init_kernel<<<1024, 256>>>(x);
    prep_kernel<<<(Q_ * C_ * 32) / 256, 256>>>(cbs);
    for (int q = 0; q < Q_; q++) {
        gemm_argmin_kernel<<<dim3(64, 8), 256>>>(q);
        update_kernel<<<256, 256>>>(cbs + (size_t)q * C_ * D_, idx_out, q,
                                    q == Q_ - 1);
    }
    final_kernel<<<512, 256>>>((const float4*)x, out, write_extra);
}

// round 6
// speedup vs baseline: 2.7477x; 1.1150x over previous
#include <cuda_runtime.h>
#include <cuda_fp16.h>
#include <cstdint>

// ---------------------------------------------------------------------------
// Problem constants
// ---------------------------------------------------------------------------
#define B_   8
#define N_   1024
#define D_   512
#define C_   1024
#define Q_   8
#define M_   (B_ * N_)      // 8192 rows
#define D4_  (D_ / 4)

// Output layout (all float32): [quantized_out M*D][indices M*Q][losses Q]
#define OUT_IDX_OFF  ((size_t)M_ * D_)
#define OUT_LOSS_OFF ((size_t)M_ * D_ + (size_t)M_ * Q_)

// ---------------------------------------------------------------------------
// Scratch (__device__ globals — allocation-free)
// ---------------------------------------------------------------------------
__device__ float g_residual[M_ * D_];
__device__ __half gA0[M_ * D_];            // residual split hi (fp16)
__device__ __half gA1[M_ * D_];            // residual split lo
__device__ __half gB0[Q_ * C_ * D_];       // codebook split hi
__device__ __half gB1[Q_ * C_ * D_];       // codebook split lo
__device__ float g_e2[Q_ * C_];
__device__ float g_loss[Q_];
__device__ unsigned long long g_argmin[M_];
__device__ int g_tile_cnt[M_ / 128];       // per-m-tile completion counters

// ---------------------------------------------------------------------------
// Arch-neutral PTX helpers (sm_80-level: cp.async / ldmatrix / mma.sync)
// ---------------------------------------------------------------------------
__device__ __forceinline__ uint32_t smem_to_u32(const void* p) {
    uint32_t a;
    asm("{ .reg .u64 t; cvta.to.shared.u64 t, %1; cvt.u32.u64 %0, t; }"
        : "=r"(a) : "l"(p));
    return a;
}
__device__ __forceinline__ void cp16(uint32_t dst, const void* src) {
    asm volatile("cp.async.cg.shared.global [%0], [%1], 16;"
                 :: "r"(dst), "l"(src));
}
#define CP_COMMIT() asm volatile("cp.async.commit_group;" ::: "memory")
#define CP_WAIT(n)  asm volatile("cp.async.wait_group %0;" :: "n"(n) : "memory")

__device__ __forceinline__ void ldm_x4(uint32_t* r, uint32_t addr) {
    asm volatile("ldmatrix.sync.aligned.m8n8.x4.shared.b16 {%0,%1,%2,%3}, [%4];"
                 : "=r"(r[0]), "=r"(r[1]), "=r"(r[2]), "=r"(r[3]) : "r"(addr));
}
__device__ __forceinline__ void mma16816(float* d, const uint32_t* a,
                                         uint32_t b0, uint32_t b1) {
    asm volatile(
        "mma.sync.aligned.m16n8k16.row.col.f32.f16.f16.f32 "
        "{%0,%1,%2,%3}, {%4,%5,%6,%7}, {%8,%9}, {%0,%1,%2,%3};"
        : "+f"(d[0]), "+f"(d[1]), "+f"(d[2]), "+f"(d[3])
        : "r"(a[0]), "r"(a[1]), "r"(a[2]), "r"(a[3]), "r"(b0), "r"(b1));
}

// ---------------------------------------------------------------------------
// fp16 double split: x = h0 + h1 + O(2^-22 x)
// ---------------------------------------------------------------------------
__device__ __forceinline__ void split2(float x, __half& h0, __half& h1) {
    h0 = __float2half_rn(x);
    h1 = __float2half_rn(x - __half2float(h0));
}

// ---------------------------------------------------------------------------
// init: residual = x (+ splits), reset argmin/counters, zero loss
// ---------------------------------------------------------------------------
__global__ void init_kernel(const float* __restrict__ x) {
    const int tid = blockIdx.x * blockDim.x + threadIdx.x;
    const int stride = gridDim.x * blockDim.x;
    for (int i = tid; i < M_ * D_; i += stride) {
        float v = x[i];
        g_residual[i] = v;
        __half h0, h1;
        split2(v, h0, h1);
        gA0[i] = h0; gA1[i] = h1;
    }
    for (int i = tid; i < M_; i += stride) g_argmin[i] = ~0ull;
    if (tid < Q_) g_loss[tid] = 0.f;
    if (tid < M_ / 128) g_tile_cnt[tid] = 0;
}

// ---------------------------------------------------------------------------
// prep: e2 + fp16 splits for all 8 codebooks (one warp per row)
// ---------------------------------------------------------------------------
__global__ void prep_kernel(const float* __restrict__ cbs) {
    const int w = (blockIdx.x * blockDim.x + threadIdx.x) >> 5;
    const int lane = threadIdx.x & 31;
    if (w >= Q_ * C_) return;
    const float* row = cbs + (size_t)w * D_;
    __half* b0 = gB0 + (size_t)w * D_;
    __half* b1 = gB1 + (size_t)w * D_;
    float s = 0.f;
#pragma unroll
    for (int i = lane; i < D_; i += 32) {
        float v = row[i];
        s = fmaf(v, v, s);
        __half h0, h1;
        split2(v, h0, h1);
        b0[i] = h0; b1[i] = h1;
    }
#pragma unroll
    for (int o = 16; o > 0; o >>= 1) s += __shfl_xor_sync(0xffffffffu, s, o);
    if (lane == 0) g_e2[w] = s;
}

// ---------------------------------------------------------------------------
// GEMM + argmin + fused update. fp16 2-split (3 products), superchunk loads:
// per k-chunk (32 elts) load A0,A1,B0,B1 once; run all 3 segment MMA passes.
// CTA tile 128x128, 8 warps @ 64x32, double-buffered cp.async.
// Last c-chunk CTA per m-tile (completion counter) performs the residual
// update / loss / re-split / index write for its 128 rows.
// ---------------------------------------------------------------------------
#define ROWB   80u             // bytes per smem row (32 fp16 + 8 pad)
#define TILEB  10240u          // 128 * 80
#define BUFB   40960u          // 4 tiles per buffer
#define NCHUNK 16

// dynamic smem layout
#define OFF_E2   81920u
#define OFF_SIDX 82432u
#define OFF_SRED 82944u
#define OFF_LAST 83968u
#define SMEM_BYTES 84000u

__global__ void __launch_bounds__(256, 2) gemm_argmin_kernel(
    const float* __restrict__ cbs, float* __restrict__ idx_out, int q, int last) {
    extern __shared__ __align__(128) char smem[];
    const uint32_t sm = smem_to_u32(smem);

    const int t = threadIdx.x;
    const int lane = t & 31, wid = t >> 5;
    const int warp_m = (wid >> 2) * 64;     // 0 or 64
    const int warp_n = (wid & 3) * 32;      // 0..96
    const int bm0 = blockIdx.x * 128;
    const int c0  = blockIdx.y * 128;

    const __half* Bq0 = gB0 + (size_t)q * C_ * D_;
    const __half* Bq1 = gB1 + (size_t)q * C_ * D_;
    float* e2s = (float*)(smem + OFF_E2);

    if (t < 128) e2s[t] = g_e2[q * C_ + c0 + t];

    // loader mapping: thread -> (row, 2 x 16B granules)
    const int lrow = t >> 1;
    const int lgr  = (t & 1) * 2;

    uint32_t a_off[4];
#pragma unroll
    for (int ma = 0; ma < 4; ma++)
        a_off[ma] = (uint32_t)((warp_m + ma * 16 + (lane & 15)) * ROWB +
                               (lane >> 4) * 16);
    uint32_t b_off[2];
#pragma unroll
    for (int p = 0; p < 2; p++)
        b_off[p] = (uint32_t)((warp_n + p * 16 + ((lane >> 4) << 3) + (lane & 7)) * ROWB +
                              ((lane >> 3) & 1) * 16);

    float acc[4][4][4];
#pragma unroll
    for (int i = 0; i < 4; i++)
#pragma unroll
        for (int j = 0; j < 4; j++)
#pragma unroll
            for (int e = 0; e < 4; e++) acc[i][j][e] = 0.f;

    auto issue_loads = [&](int kk) {
        const uint32_t buf = (kk & 1) * BUFB;
        const int col = kk * 32 + lgr * 8;
        const __half* pa0 = gA0 + (size_t)(bm0 + lrow) * D_ + col;
        const __half* pa1 = gA1 + (size_t)(bm0 + lrow) * D_ + col;
        const __half* pb0 = Bq0 + (size_t)(c0 + lrow) * D_ + col;
        const __half* pb1 = Bq1 + (size_t)(c0 + lrow) * D_ + col;
        const uint32_t base = sm + buf + lrow * ROWB + lgr * 16;
        cp16(base, pa0);                     cp16(base + 16, pa0 + 8);
        cp16(base + TILEB, pa1);             cp16(base + TILEB + 16, pa1 + 8);
        cp16(base + 2 * TILEB, pb0);         cp16(base + 2 * TILEB + 16, pb0 + 8);
        cp16(base + 3 * TILEB, pb1);         cp16(base + 3 * TILEB + 16, pb1 + 8);
        CP_COMMIT();
    };

    issue_loads(0);

    for (int cc = 0; cc < NCHUNK; cc++) {
        if (cc + 1 < NCHUNK) { issue_loads(cc + 1); CP_WAIT(1); }
        else                 { CP_WAIT(0); }
        __syncthreads();

        const uint32_t buf = sm + (cc & 1) * BUFB;
#pragma unroll
        for (int k = 0; k < 32; k += 16) {
            uint32_t a[4][4], bb[2][4];
            // A0 x B0
#pragma unroll
            for (int ma = 0; ma < 4; ma++)
                ldm_x4(a[ma], buf + a_off[ma] + k * 2);
#pragma unroll
            for (int p = 0; p < 2; p++)
                ldm_x4(bb[p], buf + 2 * TILEB + b_off[p] + k * 2);
#pragma unroll
            for (int ma = 0; ma < 4; ma++)
#pragma unroll
                for (int nb = 0; nb < 4; nb++) {
                    const uint32_t* bp = bb[nb >> 1];
                    mma16816(acc[ma][nb], a[ma], bp[(nb & 1) * 2], bp[(nb & 1) * 2 + 1]);
                }
            // A0 x B1 (reuse A frags)
#pragma unroll
            for (int p = 0; p < 2; p++)
                ldm_x4(bb[p], buf + 3 * TILEB + b_off[p] + k * 2);
#pragma unroll
            for (int ma = 0; ma < 4; ma++)
#pragma unroll
                for (int nb = 0; nb < 4; nb++) {
                    const uint32_t* bp = bb[nb >> 1];
                    mma16816(acc[ma][nb], a[ma], bp[(nb & 1) * 2], bp[(nb & 1) * 2 + 1]);
                }
            // A1 x B0
#pragma unroll
            for (int ma = 0; ma < 4; ma++)
                ldm_x4(a[ma], buf + TILEB + a_off[ma] + k * 2);
#pragma unroll
            for (int p = 0; p < 2; p++)
                ldm_x4(bb[p], buf + 2 * TILEB + b_off[p] + k * 2);
#pragma unroll
            for (int ma = 0; ma < 4; ma++)
#pragma unroll
                for (int nb = 0; nb < 4; nb++) {
                    const uint32_t* bp = bb[nb >> 1];
                    mma16816(acc[ma][nb], a[ma], bp[(nb & 1) * 2], bp[(nb & 1) * 2 + 1]);
                }
        }
        __syncthreads();
    }

    // epilogue: key = e2 - 2*dot, per-row argmin, packed atomicMin
    const int g = lane >> 2, tg = lane & 3;
#pragma unroll
    for (int ma = 0; ma < 4; ma++) {
#pragma unroll
        for (int half = 0; half < 2; half++) {
            float bv = 3.4e38f;
            int bi = 0;
#pragma unroll
            for (int nb = 0; nb < 4; nb++) {
#pragma unroll
                for (int e2i = 0; e2i < 2; e2i++) {
                    const int cloc = warp_n + nb * 8 + tg * 2 + e2i;
                    float key = fmaf(-2.f, acc[ma][nb][half * 2 + e2i], e2s[cloc]);
                    if (key < bv) { bv = key; bi = c0 + cloc; }
                }
            }
            uint32_t u = __float_as_uint(bv);
            u = (u & 0x80000000u) ? ~u : (u | 0x80000000u);
            unsigned long long pk = ((unsigned long long)u << 32) | (unsigned)bi;
#pragma unroll
            for (int o = 1; o <= 2; o <<= 1) {
                unsigned long long other = __shfl_xor_sync(0xffffffffu, pk, o);
                if (other < pk) pk = other;
            }
            if (tg == 0)
                atomicMin(&g_argmin[bm0 + warp_m + ma * 16 + half * 8 + g], pk);
        }
    }

    // completion counter: last of the 8 c-chunk CTAs does the fused update
    __syncthreads();
    int* s_last = (int*)(smem + OFF_LAST);
    if (t == 0) {
        __threadfence();
        *s_last = (atomicAdd(&g_tile_cnt[blockIdx.x], 1) == 7);
    }
    __syncthreads();
    if (!*s_last) return;

    if (t == 0) g_tile_cnt[blockIdx.x] = 0;   // reset for next layer / replay
    __threadfence();

    int* sidx = (int*)(smem + OFF_SIDX);
    if (t < 128) {
        // atomicExch: coherent read of the final min AND reset for next layer
        unsigned long long v = atomicExch(&g_argmin[bm0 + t], ~0ull);
        int c = (int)(v & 0xFFFFFFFFull);
        sidx[t] = c;
        if (idx_out) idx_out[(size_t)(bm0 + t) * Q_ + q] = (float)c;
    }
    __syncthreads();

    const float* cb = cbs + (size_t)q * C_ * D_;
    float sq = 0.f;
    for (int i = t; i < 128 * D4_; i += 256) {
        const int row = i >> 7, j = i & 127;
        const int idx = sidx[row];
        const size_t rg = (size_t)(bm0 + row) * D4_ + j;
        float4 rv = ((float4*)g_residual)[rg];
        const float4 cv = ((const float4*)cb)[(size_t)idx * D4_ + j];
        rv.x -= cv.x; rv.y -= cv.y; rv.z -= cv.z; rv.w -= cv.w;
        ((float4*)g_residual)[rg] = rv;
        sq = fmaf(rv.x, rv.x, sq); sq = fmaf(rv.y, rv.y, sq);
        sq = fmaf(rv.z, rv.z, sq); sq = fmaf(rv.w, rv.w, sq);
        if (!last) {
            const size_t e = (size_t)(bm0 + row) * D_ + (size_t)j * 4;
            float vals[4] = {rv.x, rv.y, rv.z, rv.w};
            uint32_t p0[2], p1[2];
#pragma unroll
            for (int hp = 0; hp < 2; hp++) {
                __half a0h, a1h, b0h, b1h;
                split2(vals[2 * hp], a0h, a1h);
                split2(vals[2 * hp + 1], b0h, b1h);
                p0[hp] = (uint32_t)__half_as_ushort(a0h) |
                         ((uint32_t)__half_as_ushort(b0h) << 16);
                p1[hp] = (uint32_t)__half_as_ushort(a1h) |
                         ((uint32_t)__half_as_ushort(b1h) << 16);
            }
            *(uint2*)&gA0[e] = make_uint2(p0[0], p0[1]);
            *(uint2*)&gA1[e] = make_uint2(p1[0], p1[1]);
        }
    }
    float* sred = (float*)(smem + OFF_SRED);
    sred[t] = sq;
    __syncthreads();
    for (int o = 128; o > 0; o >>= 1) {
        if (t < o) sred[t] += sred[t + o];
        __syncthreads();
    }
    if (t == 0) atomicAdd(&g_loss[q], sred[0]);
}

// ---------------------------------------------------------------------------
// final: quantized_out = x - residual_final; write losses
// ---------------------------------------------------------------------------
__global__ void final_kernel(const float4* __restrict__ x,
                             float* __restrict__ out, int write_extra) {
    const int n4 = M_ * D_ / 4;
    float4* o4 = (float4*)out;
    const float4* r4 = (const float4*)g_residual;
    for (int i = blockIdx.x * blockDim.x + threadIdx.x; i < n4;
         i += gridDim.x * blockDim.x) {
        float4 xv = x[i], rv = r4[i];
        float4 ov;
        ov.x = xv.x - rv.x; ov.y = xv.y - rv.y;
        ov.z = xv.z - rv.z; ov.w = xv.w - rv.w;
        o4[i] = ov;
    }
    if (write_extra && blockIdx.x == 0 && threadIdx.x < Q_)
        out[OUT_LOSS_OFF + threadIdx.x] =
            g_loss[threadIdx.x] * (1.0f / ((float)M_ * (float)D_));
}

// ---------------------------------------------------------------------------
extern "C" void kernel_launch(void* const* d_in, const int* in_sizes, int n_in,
                              void* d_out, int out_size) {
    const float* x   = (const float*)d_in[0];
    const float* cbs = (const float*)d_in[1];
    float* out = (float*)d_out;

    const int full = (int)(OUT_LOSS_OFF + Q_);
    const int write_extra = (out_size >= full) ? 1 : 0;
    float* idx_out = write_extra ? out + OUT_IDX_OFF : nullptr;

    static int attr_done = 0;
    if (!attr_done) {
        cudaFuncSetAttribute(gemm_argmin_kernel,
                             cudaFuncAttributeMaxDynamicSharedMemorySize,
                             SMEM_BYTES);
        attr_done = 1;
    }

    init_kernel<<<1024, 256>>>(x);
    prep_kernel<<<(Q_ * C_ * 32) / 256, 256>>>(cbs);
    for (int q = 0; q < Q_; q++)
        gemm_argmin_kernel<<<dim3(64, 8), 256, SMEM_BYTES>>>(cbs, idx_out, q,
                                                             q == Q_ - 1);
    final_kernel<<<512, 256>>>((const float4*)x, out, write_extra);
}

// round 7
// speedup vs baseline: 2.9168x; 1.0615x over previous
#include <cuda_runtime.h>
#include <cuda_fp16.h>
#include <cstdint>

// ---------------------------------------------------------------------------
// Problem constants
// ---------------------------------------------------------------------------
#define B_   8
#define N_   1024
#define D_   512
#define C_   1024
#define Q_   8
#define M_   (B_ * N_)      // 8192 rows
#define D4_  (D_ / 4)

// Output layout (all float32): [quantized_out M*D][indices M*Q][losses Q]
#define OUT_IDX_OFF  ((size_t)M_ * D_)
#define OUT_LOSS_OFF ((size_t)M_ * D_ + (size_t)M_ * Q_)

// ---------------------------------------------------------------------------
// Scratch (__device__ globals — allocation-free)
// ---------------------------------------------------------------------------
__device__ float g_residual[M_ * D_];
__device__ __half gA0[M_ * D_];            // residual split hi (fp16)
__device__ __half gA1[M_ * D_];            // residual split lo
__device__ __half gB0[Q_ * C_ * D_];       // codebook split hi
__device__ __half gB1[Q_ * C_ * D_];       // codebook split lo
__device__ float g_e2[Q_ * C_];
__device__ float g_loss[Q_];
__device__ unsigned long long g_argmin[M_];
__device__ int g_tile_cnt[M_ / 128];       // per-m-tile completion counters

// ---------------------------------------------------------------------------
// Arch-neutral PTX helpers (sm_80-level: cp.async / ldmatrix / mma.sync)
// ---------------------------------------------------------------------------
__device__ __forceinline__ uint32_t smem_to_u32(const void* p) {
    uint32_t a;
    asm("{ .reg .u64 t; cvta.to.shared.u64 t, %1; cvt.u32.u64 %0, t; }"
        : "=r"(a) : "l"(p));
    return a;
}
__device__ __forceinline__ void cp16(uint32_t dst, const void* src) {
    asm volatile("cp.async.cg.shared.global [%0], [%1], 16;"
                 :: "r"(dst), "l"(src));
}
#define CP_COMMIT() asm volatile("cp.async.commit_group;" ::: "memory")
#define CP_WAIT(n)  asm volatile("cp.async.wait_group %0;" :: "n"(n) : "memory")

__device__ __forceinline__ void ldm_x4(uint32_t* r, uint32_t addr) {
    asm volatile("ldmatrix.sync.aligned.m8n8.x4.shared.b16 {%0,%1,%2,%3}, [%4];"
                 : "=r"(r[0]), "=r"(r[1]), "=r"(r[2]), "=r"(r[3]) : "r"(addr));
}
__device__ __forceinline__ void mma16816(float* d, const uint32_t* a,
                                         uint32_t b0, uint32_t b1) {
    asm volatile(
        "mma.sync.aligned.m16n8k16.row.col.f32.f16.f16.f32 "
        "{%0,%1,%2,%3}, {%4,%5,%6,%7}, {%8,%9}, {%0,%1,%2,%3};"
        : "+f"(d[0]), "+f"(d[1]), "+f"(d[2]), "+f"(d[3])
        : "r"(a[0]), "r"(a[1]), "r"(a[2]), "r"(a[3]), "r"(b0), "r"(b1));
}

// ---------------------------------------------------------------------------
// fp16 double split: x = h0 + h1 + O(2^-22 x)
// ---------------------------------------------------------------------------
__device__ __forceinline__ void split2(float x, __half& h0, __half& h1) {
    h0 = __float2half_rn(x);
    h1 = __float2half_rn(x - __half2float(h0));
}

// ---------------------------------------------------------------------------
// init: residual = x (+ splits), reset argmin/counters, zero loss
// ---------------------------------------------------------------------------
__global__ void init_kernel(const float* __restrict__ x) {
    const int tid = blockIdx.x * blockDim.x + threadIdx.x;
    const int stride = gridDim.x * blockDim.x;
    for (int i = tid; i < M_ * D_; i += stride) {
        float v = x[i];
        g_residual[i] = v;
        __half h0, h1;
        split2(v, h0, h1);
        gA0[i] = h0; gA1[i] = h1;
    }
    for (int i = tid; i < M_; i += stride) g_argmin[i] = ~0ull;
    if (tid < Q_) g_loss[tid] = 0.f;
    if (tid < M_ / 128) g_tile_cnt[tid] = 0;
}

// ---------------------------------------------------------------------------
// prep: e2 + fp16 splits for all 8 codebooks (one warp per row)
// ---------------------------------------------------------------------------
__global__ void prep_kernel(const float* __restrict__ cbs) {
    const int w = (blockIdx.x * blockDim.x + threadIdx.x) >> 5;
    const int lane = threadIdx.x & 31;
    if (w >= Q_ * C_) return;
    const float* row = cbs + (size_t)w * D_;
    __half* b0 = gB0 + (size_t)w * D_;
    __half* b1 = gB1 + (size_t)w * D_;
    float s = 0.f;
#pragma unroll
    for (int i = lane; i < D_; i += 32) {
        float v = row[i];
        s = fmaf(v, v, s);
        __half h0, h1;
        split2(v, h0, h1);
        b0[i] = h0; b1[i] = h1;
    }
#pragma unroll
    for (int o = 16; o > 0; o >>= 1) s += __shfl_xor_sync(0xffffffffu, s, o);
    if (lane == 0) g_e2[w] = s;
}

// ---------------------------------------------------------------------------
// GEMM + argmin + fused update. fp16 2-split (3 products A0B0+A0B1+A1B0).
// 4-stage cp.async pipeline, k-chunk 16, ONE __syncthreads per chunk.
// CTA tile 128x128, 8 warps @ 64x32. Per chunk: load B0,B1,A0 frags once,
// MMA A0B0 + A0B1, overwrite A frags with A1, MMA A1B0 (12 LDSM/chunk).
// Last c-chunk CTA per m-tile (counter) does residual update for 128 rows.
// ---------------------------------------------------------------------------
#define KCH    16
#define NCH    32              // 512 / 16
#define STAGES 4
#define ROWB   48u             // 16 fp16 (32B) + 16B pad
#define TILEB  6144u           // 128 * 48
#define STAGEB 24576u          // 4 tiles (A0,A1,B0,B1)

// dynamic smem layout
#define OFF_E2   98304u
#define OFF_SIDX 98816u
#define OFF_SRED 99328u
#define OFF_LAST 100352u
#define SMEM_BYTES 100368u

__global__ void __launch_bounds__(256, 2) gemm_argmin_kernel(
    const float* __restrict__ cbs, float* __restrict__ idx_out, int q, int last) {
    extern __shared__ __align__(128) char smem[];
    const uint32_t sm = smem_to_u32(smem);

    const int t = threadIdx.x;
    const int lane = t & 31, wid = t >> 5;
    const int warp_m = (wid >> 2) * 64;     // 0 or 64
    const int warp_n = (wid & 3) * 32;      // 0..96
    const int bm0 = blockIdx.x * 128;
    const int c0  = blockIdx.y * 128;

    const __half* Bq0 = gB0 + (size_t)q * C_ * D_;
    const __half* Bq1 = gB1 + (size_t)q * C_ * D_;
    float* e2s = (float*)(smem + OFF_E2);

    if (t < 128) e2s[t] = g_e2[q * C_ + c0 + t];

    // loader mapping: thread -> (row, one 16B granule per tile)
    const int lrow = (t >> 1) & 127;
    const int lg   = t & 1;

    uint32_t a_off[4];
#pragma unroll
    for (int ma = 0; ma < 4; ma++)
        a_off[ma] = (uint32_t)((warp_m + ma * 16 + (lane & 15)) * ROWB +
                               (lane >> 4) * 16);
    uint32_t b_off[2];
#pragma unroll
    for (int p = 0; p < 2; p++)
        b_off[p] = (uint32_t)((warp_n + p * 16 + ((lane >> 4) << 3) + (lane & 7)) * ROWB +
                              ((lane >> 3) & 1) * 16);

    float acc[4][4][4];
#pragma unroll
    for (int i = 0; i < 4; i++)
#pragma unroll
        for (int j = 0; j < 4; j++)
#pragma unroll
            for (int e = 0; e < 4; e++) acc[i][j][e] = 0.f;

    // per-thread global source pointers (row fixed, col advances)
    const __half* pa0 = gA0 + (size_t)(bm0 + lrow) * D_ + lg * 8;
    const __half* pa1 = gA1 + (size_t)(bm0 + lrow) * D_ + lg * 8;
    const __half* pb0 = Bq0 + (size_t)(c0 + lrow) * D_ + lg * 8;
    const __half* pb1 = Bq1 + (size_t)(c0 + lrow) * D_ + lg * 8;
    const uint32_t sdst = sm + lrow * ROWB + lg * 16;

    auto issue_loads = [&](int kk) {
        const uint32_t buf = (uint32_t)(kk & 3) * STAGEB + sdst;
        const int col = kk * KCH;
        cp16(buf,             pa0 + col);
        cp16(buf + TILEB,     pa1 + col);
        cp16(buf + 2 * TILEB, pb0 + col);
        cp16(buf + 3 * TILEB, pb1 + col);
        CP_COMMIT();
    };

    issue_loads(0); issue_loads(1); issue_loads(2);

    for (int cc = 0; cc < NCH; cc++) {
        if (cc < NCH - 2)      CP_WAIT(2);
        else if (cc == NCH - 2) CP_WAIT(1);
        else                    CP_WAIT(0);
        __syncthreads();

        const uint32_t buf = sm + (uint32_t)(cc & 3) * STAGEB;
        uint32_t a[4][4], b0f[2][4], b1f[2][4];
#pragma unroll
        for (int p = 0; p < 2; p++) ldm_x4(b0f[p], buf + 2 * TILEB + b_off[p]);
#pragma unroll
        for (int p = 0; p < 2; p++) ldm_x4(b1f[p], buf + 3 * TILEB + b_off[p]);
#pragma unroll
        for (int ma = 0; ma < 4; ma++) ldm_x4(a[ma], buf + a_off[ma]);
        // A0 x B0  and  A0 x B1
#pragma unroll
        for (int ma = 0; ma < 4; ma++)
#pragma unroll
            for (int nb = 0; nb < 4; nb++) {
                const uint32_t* bp = b0f[nb >> 1];
                mma16816(acc[ma][nb], a[ma], bp[(nb & 1) * 2], bp[(nb & 1) * 2 + 1]);
            }
#pragma unroll
        for (int ma = 0; ma < 4; ma++)
#pragma unroll
            for (int nb = 0; nb < 4; nb++) {
                const uint32_t* bp = b1f[nb >> 1];
                mma16816(acc[ma][nb], a[ma], bp[(nb & 1) * 2], bp[(nb & 1) * 2 + 1]);
            }
        // A1 x B0 (overwrite A frags)
#pragma unroll
        for (int ma = 0; ma < 4; ma++) ldm_x4(a[ma], buf + TILEB + a_off[ma]);
#pragma unroll
        for (int ma = 0; ma < 4; ma++)
#pragma unroll
            for (int nb = 0; nb < 4; nb++) {
                const uint32_t* bp = b0f[nb >> 1];
                mma16816(acc[ma][nb], a[ma], bp[(nb & 1) * 2], bp[(nb & 1) * 2 + 1]);
            }

        if (cc + 3 < NCH) issue_loads(cc + 3);
    }

    // epilogue: key = e2 - 2*dot, per-row argmin, packed atomicMin
    const int g = lane >> 2, tg = lane & 3;
#pragma unroll
    for (int ma = 0; ma < 4; ma++) {
#pragma unroll
        for (int half = 0; half < 2; half++) {
            float bv = 3.4e38f;
            int bi = 0;
#pragma unroll
            for (int nb = 0; nb < 4; nb++) {
#pragma unroll
                for (int e2i = 0; e2i < 2; e2i++) {
                    const int cloc = warp_n + nb * 8 + tg * 2 + e2i;
                    float key = fmaf(-2.f, acc[ma][nb][half * 2 + e2i], e2s[cloc]);
                    if (key < bv) { bv = key; bi = c0 + cloc; }
                }
            }
            uint32_t u = __float_as_uint(bv);
            u = (u & 0x80000000u) ? ~u : (u | 0x80000000u);
            unsigned long long pk = ((unsigned long long)u << 32) | (unsigned)bi;
#pragma unroll
            for (int o = 1; o <= 2; o <<= 1) {
                unsigned long long other = __shfl_xor_sync(0xffffffffu, pk, o);
                if (other < pk) pk = other;
            }
            if (tg == 0)
                atomicMin(&g_argmin[bm0 + warp_m + ma * 16 + half * 8 + g], pk);
        }
    }

    // completion counter: last of the 8 c-chunk CTAs does the fused update
    __syncthreads();
    int* s_last = (int*)(smem + OFF_LAST);
    if (t == 0) {
        __threadfence();
        *s_last = (atomicAdd(&g_tile_cnt[blockIdx.x], 1) == 7);
    }
    __syncthreads();
    if (!*s_last) return;

    if (t == 0) g_tile_cnt[blockIdx.x] = 0;   // reset for next layer / replay
    __threadfence();

    int* sidx = (int*)(smem + OFF_SIDX);
    if (t < 128) {
        // atomicExch: coherent read of the final min AND reset for next layer
        unsigned long long v = atomicExch(&g_argmin[bm0 + t], ~0ull);
        int c = (int)(v & 0xFFFFFFFFull);
        sidx[t] = c;
        if (idx_out) idx_out[(size_t)(bm0 + t) * Q_ + q] = (float)c;
    }
    __syncthreads();

    const float* cb = cbs + (size_t)q * C_ * D_;
    float sq = 0.f;
    for (int i = t; i < 128 * D4_; i += 256) {
        const int row = i >> 7, j = i & 127;
        const int idx = sidx[row];
        const size_t rg = (size_t)(bm0 + row) * D4_ + j;
        float4 rv = ((float4*)g_residual)[rg];
        const float4 cv = ((const float4*)cb)[(size_t)idx * D4_ + j];
        rv.x -= cv.x; rv.y -= cv.y; rv.z -= cv.z; rv.w -= cv.w;
        ((float4*)g_residual)[rg] = rv;
        sq = fmaf(rv.x, rv.x, sq); sq = fmaf(rv.y, rv.y, sq);
        sq = fmaf(rv.z, rv.z, sq); sq = fmaf(rv.w, rv.w, sq);
        if (!last) {
            const size_t e = (size_t)(bm0 + row) * D_ + (size_t)j * 4;
            float vals[4] = {rv.x, rv.y, rv.z, rv.w};
            uint32_t p0[2], p1[2];
#pragma unroll
            for (int hp = 0; hp < 2; hp++) {
                __half a0h, a1h, b0h, b1h;
                split2(vals[2 * hp], a0h, a1h);
                split2(vals[2 * hp + 1], b0h, b1h);
                p0[hp] = (uint32_t)__half_as_ushort(a0h) |
                         ((uint32_t)__half_as_ushort(b0h) << 16);
                p1[hp] = (uint32_t)__half_as_ushort(a1h) |
                         ((uint32_t)__half_as_ushort(b1h) << 16);
            }
            *(uint2*)&gA0[e] = make_uint2(p0[0], p0[1]);
            *(uint2*)&gA1[e] = make_uint2(p1[0], p1[1]);
        }
    }
    float* sred = (float*)(smem + OFF_SRED);
    sred[t] = sq;
    __syncthreads();
    for (int o = 128; o > 0; o >>= 1) {
        if (t < o) sred[t] += sred[t + o];
        __syncthreads();
    }
    if (t == 0) atomicAdd(&g_loss[q], sred[0]);
}

// ---------------------------------------------------------------------------
// final: quantized_out = x - residual_final; write losses
// ---------------------------------------------------------------------------
__global__ void final_kernel(const float4* __restrict__ x,
                             float* __restrict__ out, int write_extra) {
    const int n4 = M_ * D_ / 4;
    float4* o4 = (float4*)out;
    const float4* r4 = (const float4*)g_residual;
    for (int i = blockIdx.x * blockDim.x + threadIdx.x; i < n4;
         i += gridDim.x * blockDim.x) {
        float4 xv = x[i], rv = r4[i];
        float4 ov;
        ov.x = xv.x - rv.x; ov.y = xv.y - rv.y;
        ov.z = xv.z - rv.z; ov.w = xv.w - rv.w;
        o4[i] = ov;
    }
    if (write_extra && blockIdx.x == 0 && threadIdx.x < Q_)
        out[OUT_LOSS_OFF + threadIdx.x] =
            g_loss[threadIdx.x] * (1.0f / ((float)M_ * (float)D_));
}

// ---------------------------------------------------------------------------
extern "C" void kernel_launch(void* const* d_in, const int* in_sizes, int n_in,
                              void* d_out, int out_size) {
    const float* x   = (const float*)d_in[0];
    const float* cbs = (const float*)d_in[1];
    float* out = (float*)d_out;

    const int full = (int)(OUT_LOSS_OFF + Q_);
    const int write_extra = (out_size >= full) ? 1 : 0;
    float* idx_out = write_extra ? out + OUT_IDX_OFF : nullptr;

    static int attr_done = 0;
    if (!attr_done) {
        cudaFuncSetAttribute(gemm_argmin_kernel,
                             cudaFuncAttributeMaxDynamicSharedMemorySize,
                             SMEM_BYTES);
        attr_done = 1;
    }

    init_kernel<<<1024, 256>>>(x);
    prep_kernel<<<(Q_ * C_ * 32) / 256, 256>>>(cbs);
    for (int q = 0; q < Q_; q++)
        gemm_argmin_kernel<<<dim3(64, 8), 256, SMEM_BYTES>>>(cbs, idx_out, q,
                                                             q == Q_ - 1);
    final_kernel<<<512, 256>>>((const float4*)x, out, write_extra);
}

// round 8
// speedup vs baseline: 5.6430x; 1.9347x over previous
#include <cuda_runtime.h>
#include <cuda_fp16.h>
#include <cstdint>

// ---------------------------------------------------------------------------
// Problem constants
// ---------------------------------------------------------------------------
#define B_   8
#define N_   1024
#define D_   512
#define C_   1024
#define Q_   8
#define M_   (B_ * N_)      // 8192 rows
#define D4_  (D_ / 4)

// Output layout (all float32): [quantized_out M*D][indices M*Q][losses Q]
#define OUT_IDX_OFF  ((size_t)M_ * D_)
#define OUT_LOSS_OFF ((size_t)M_ * D_ + (size_t)M_ * Q_)

// rescue margin for the approx screen (worst-case key error ~0.16)
#define DELTA 0.5f

// ---------------------------------------------------------------------------
// Scratch (__device__ globals — allocation-free)
// ---------------------------------------------------------------------------
__device__ float g_residual[M_ * D_];
__device__ __half gA0[M_ * D_];            // fp16(residual)
__device__ __half gB0[Q_ * C_ * D_];       // fp16(codebooks)
__device__ float g_e2[Q_ * C_];
__device__ float g_loss[Q_];
__device__ float g_keys[M_ * C_];          // approx keys e2 - 2*dot (33.5 MB)

// ---------------------------------------------------------------------------
// Arch-neutral PTX helpers (sm_80-level: cp.async / ldmatrix / mma.sync)
// ---------------------------------------------------------------------------
__device__ __forceinline__ uint32_t smem_to_u32(const void* p) {
    uint32_t a;
    asm("{ .reg .u64 t; cvta.to.shared.u64 t, %1; cvt.u32.u64 %0, t; }"
        : "=r"(a) : "l"(p));
    return a;
}
__device__ __forceinline__ void cp16(uint32_t dst, const void* src) {
    asm volatile("cp.async.cg.shared.global [%0], [%1], 16;"
                 :: "r"(dst), "l"(src));
}
#define CP_COMMIT() asm volatile("cp.async.commit_group;" ::: "memory")
#define CP_WAIT(n)  asm volatile("cp.async.wait_group %0;" :: "n"(n) : "memory")

__device__ __forceinline__ void ldm_x4(uint32_t* r, uint32_t addr) {
    asm volatile("ldmatrix.sync.aligned.m8n8.x4.shared.b16 {%0,%1,%2,%3}, [%4];"
                 : "=r"(r[0]), "=r"(r[1]), "=r"(r[2]), "=r"(r[3]) : "r"(addr));
}
__device__ __forceinline__ void mma16816(float* d, const uint32_t* a,
                                         uint32_t b0, uint32_t b1) {
    asm volatile(
        "mma.sync.aligned.m16n8k16.row.col.f32.f16.f16.f32 "
        "{%0,%1,%2,%3}, {%4,%5,%6,%7}, {%8,%9}, {%0,%1,%2,%3};"
        : "+f"(d[0]), "+f"(d[1]), "+f"(d[2]), "+f"(d[3])
        : "r"(a[0]), "r"(a[1]), "r"(a[2]), "r"(a[3]), "r"(b0), "r"(b1));
}

// monotone float -> uint transform (order-preserving, for packed min)
__device__ __forceinline__ uint32_t ford(float f) {
    uint32_t u = __float_as_uint(f);
    return (u & 0x80000000u) ? ~u : (u | 0x80000000u);
}
__device__ __forceinline__ float funord(uint32_t u) {
    return __uint_as_float((u & 0x80000000u) ? (u ^ 0x80000000u) : ~u);
}

// ---------------------------------------------------------------------------
// init: residual = x, fp16 copy, zero loss
// ---------------------------------------------------------------------------
__global__ void init_kernel(const float* __restrict__ x) {
    const int tid = blockIdx.x * blockDim.x + threadIdx.x;
    const int stride = gridDim.x * blockDim.x;
    for (int i = tid; i < M_ * D_; i += stride) {
        float v = x[i];
        g_residual[i] = v;
        gA0[i] = __float2half_rn(v);
    }
    if (tid < Q_) g_loss[tid] = 0.f;
}

// ---------------------------------------------------------------------------
// prep: e2 + fp16 copy for all 8 codebooks (one warp per row)
// ---------------------------------------------------------------------------
__global__ void prep_kernel(const float* __restrict__ cbs) {
    const int w = (blockIdx.x * blockDim.x + threadIdx.x) >> 5;
    const int lane = threadIdx.x & 31;
    if (w >= Q_ * C_) return;
    const float* row = cbs + (size_t)w * D_;
    __half* b0 = gB0 + (size_t)w * D_;
    float s = 0.f;
#pragma unroll
    for (int i = lane; i < D_; i += 32) {
        float v = row[i];
        s = fmaf(v, v, s);
        b0[i] = __float2half_rn(v);
    }
#pragma unroll
    for (int o = 16; o > 0; o >>= 1) s += __shfl_xor_sync(0xffffffffu, s, o);
    if (lane == 0) g_e2[w] = s;
}

// ---------------------------------------------------------------------------
// Screen GEMM: single fp16 product, fp32 accumulate. CTA 128x128, K=512,
// 8 warps @ 64x32, 4-stage cp.async pipeline, k-chunk 32.
// Epilogue writes approx keys (e2 - 2*dot) to g_keys. No atomics.
// ---------------------------------------------------------------------------
#define KCH    32
#define NCH    16              // 512 / 32
#define ROWB   80u             // 32 fp16 (64B) + 16B pad
#define TILEB  10240u          // 128 * 80
#define STAGEB 20480u          // A + B tiles
#define OFF_E2 81920u
#define SMEM_BYTES 82432u

__global__ void __launch_bounds__(256, 2) screen_kernel(int q) {
    extern __shared__ __align__(128) char smem[];
    const uint32_t sm = smem_to_u32(smem);

    const int t = threadIdx.x;
    const int lane = t & 31, wid = t >> 5;
    const int warp_m = (wid >> 2) * 64;     // 0 or 64
    const int warp_n = (wid & 3) * 32;      // 0..96
    const int bm0 = blockIdx.x * 128;
    const int c0  = blockIdx.y * 128;

    const __half* Bq0 = gB0 + (size_t)q * C_ * D_;
    float* e2s = (float*)(smem + OFF_E2);
    if (t < 128) e2s[t] = g_e2[q * C_ + c0 + t];

    // loader mapping: row = t>>1 (128 rows), granule g = t&1 (32B half-row)
    const int lrow = t >> 1;
    const int lg   = t & 1;
    const __half* pa = gA0 + (size_t)(bm0 + lrow) * D_ + lg * 16;
    const __half* pb = Bq0 + (size_t)(c0 + lrow) * D_ + lg * 16;
    const uint32_t sdst = sm + lrow * ROWB + lg * 32;

    uint32_t a_off[4];
#pragma unroll
    for (int ma = 0; ma < 4; ma++)
        a_off[ma] = (uint32_t)((warp_m + ma * 16 + (lane & 15)) * ROWB +
                               (lane >> 4) * 16);
    uint32_t b_off[2];
#pragma unroll
    for (int p = 0; p < 2; p++)
        b_off[p] = (uint32_t)((warp_n + p * 16 + ((lane >> 4) << 3) + (lane & 7)) * ROWB +
                              ((lane >> 3) & 1) * 16);

    float acc[4][4][4];
#pragma unroll
    for (int i = 0; i < 4; i++)
#pragma unroll
        for (int j = 0; j < 4; j++)
#pragma unroll
            for (int e = 0; e < 4; e++) acc[i][j][e] = 0.f;

    auto issue_loads = [&](int kk) {
        const uint32_t buf = (uint32_t)(kk & 3) * STAGEB + sdst;
        const int col = kk * KCH;
        cp16(buf,              pa + col);
        cp16(buf + 16,         pa + col + 8);
        cp16(buf + TILEB,      pb + col);
        cp16(buf + TILEB + 16, pb + col + 8);
        CP_COMMIT();
    };

    issue_loads(0); issue_loads(1); issue_loads(2);

    for (int cc = 0; cc < NCH; cc++) {
        if (cc < NCH - 2)       CP_WAIT(2);
        else if (cc == NCH - 2) CP_WAIT(1);
        else                    CP_WAIT(0);
        __syncthreads();

        const uint32_t buf = sm + (uint32_t)(cc & 3) * STAGEB;
#pragma unroll
        for (int k = 0; k < 2; k++) {           // two k=16 steps (bytes +0/+32)
            uint32_t a[4][4], bb[2][4];
#pragma unroll
            for (int ma = 0; ma < 4; ma++)
                ldm_x4(a[ma], buf + a_off[ma] + k * 32);
#pragma unroll
            for (int p = 0; p < 2; p++)
                ldm_x4(bb[p], buf + TILEB + b_off[p] + k * 32);
#pragma unroll
            for (int ma = 0; ma < 4; ma++)
#pragma unroll
                for (int nb = 0; nb < 4; nb++) {
                    const uint32_t* bp = bb[nb >> 1];
                    mma16816(acc[ma][nb], a[ma], bp[(nb & 1) * 2], bp[(nb & 1) * 2 + 1]);
                }
        }
        if (cc + 3 < NCH) issue_loads(cc + 3);
        __syncthreads();
    }

    // epilogue: write approx keys (float2 stores)
    const int g = lane >> 2, tg = lane & 3;
#pragma unroll
    for (int ma = 0; ma < 4; ma++) {
#pragma unroll
        for (int half = 0; half < 2; half++) {
            const int row = bm0 + warp_m + ma * 16 + half * 8 + g;
            float* krow = g_keys + (size_t)row * C_ + c0 + warp_n;
#pragma unroll
            for (int nb = 0; nb < 4; nb++) {
                const int cloc = warp_n + nb * 8 + tg * 2;
                float2 kv;
                kv.x = fmaf(-2.f, acc[ma][nb][half * 2 + 0], e2s[cloc]);
                kv.y = fmaf(-2.f, acc[ma][nb][half * 2 + 1], e2s[cloc + 1]);
                *(float2*)(krow + nb * 8 + tg * 2) = kv;
            }
        }
    }
}

// ---------------------------------------------------------------------------
// rerank + update: one warp per row. Scan approx keys, exact fp32 re-rank of
// candidates within DELTA of the row min, then residual update / loss /
// fp16 re-copy / index write.
// ---------------------------------------------------------------------------
__global__ void __launch_bounds__(256) rerank_kernel(
    const float* __restrict__ cbs, float* __restrict__ idx_out, int q, int last) {
    const int lane = threadIdx.x & 31, wid = threadIdx.x >> 5;
    const int row = blockIdx.x * 8 + wid;
    const float* cb = cbs + (size_t)q * C_ * D_;
    __shared__ float wsum[8];

    // residual row, lane-strided
    float res[16];
#pragma unroll
    for (int k = 0; k < 16; k++)
        res[k] = g_residual[(size_t)row * D_ + lane + 32 * k];

    // load this lane's 32 keys
    const float* krow = g_keys + (size_t)row * C_;
    float keys[32];
#pragma unroll
    for (int kp = 0; kp < 32; kp++) keys[kp] = krow[kp * 32 + lane];

    // packed min over the row (tie -> smallest index)
    unsigned long long pk = ~0ull;
#pragma unroll
    for (int kp = 0; kp < 32; kp++) {
        unsigned long long p =
            ((unsigned long long)ford(keys[kp]) << 32) | (unsigned)(kp * 32 + lane);
        if (p < pk) pk = p;
    }
#pragma unroll
    for (int o = 16; o > 0; o >>= 1) {
        unsigned long long other = __shfl_xor_sync(0xffffffffu, pk, o);
        if (other < pk) pk = other;
    }
    const float thresh = funord((uint32_t)(pk >> 32)) + DELTA;

    // exact re-rank of margin candidates
    unsigned long long bestx = ~0ull;
#pragma unroll
    for (int kp = 0; kp < 32; kp++) {
        unsigned mask = __ballot_sync(0xffffffffu, keys[kp] <= thresh);
        while (mask) {
            const int b = __ffs(mask) - 1;
            mask &= mask - 1;
            const int cand = kp * 32 + b;
            const float* cr = cb + (size_t)cand * D_;
            float dot = 0.f;
#pragma unroll
            for (int k = 0; k < 16; k++)
                dot = fmaf(res[k], cr[lane + 32 * k], dot);
#pragma unroll
            for (int o = 16; o > 0; o >>= 1)
                dot += __shfl_xor_sync(0xffffffffu, dot, o);
            const float ek = g_e2[q * C_ + cand] - 2.f * dot;
            unsigned long long p =
                ((unsigned long long)ford(ek) << 32) | (unsigned)cand;
            if (p < bestx) bestx = p;
        }
    }
    const int bidx = (int)(bestx & 0xFFFFFFFFull);
    if (lane == 0 && idx_out)
        idx_out[(size_t)row * Q_ + q] = (float)bidx;

    // update residual, loss, fp16 copy
    const float* cw = cb + (size_t)bidx * D_;
    float sq = 0.f;
#pragma unroll
    for (int k = 0; k < 16; k++) {
        const int j = lane + 32 * k;
        float rn = res[k] - cw[j];
        g_residual[(size_t)row * D_ + j] = rn;
        sq = fmaf(rn, rn, sq);
        if (!last) gA0[(size_t)row * D_ + j] = __float2half_rn(rn);
    }
#pragma unroll
    for (int o = 16; o > 0; o >>= 1) sq += __shfl_xor_sync(0xffffffffu, sq, o);
    if (lane == 0) wsum[wid] = sq;
    __syncthreads();
    if (threadIdx.x == 0) {
        float s = 0.f;
#pragma unroll
        for (int w = 0; w < 8; w++) s += wsum[w];
        atomicAdd(&g_loss[q], s);
    }
}

// ---------------------------------------------------------------------------
// final: quantized_out = x - residual_final; write losses
// ---------------------------------------------------------------------------
__global__ void final_kernel(const float4* __restrict__ x,
                             float* __restrict__ out, int write_extra) {
    const int n4 = M_ * D_ / 4;
    float4* o4 = (float4*)out;
    const float4* r4 = (const float4*)g_residual;
    for (int i = blockIdx.x * blockDim.x + threadIdx.x; i < n4;
         i += gridDim.x * blockDim.x) {
        float4 xv = x[i], rv = r4[i];
        float4 ov;
        ov.x = xv.x - rv.x; ov.y = xv.y - rv.y;
        ov.z = xv.z - rv.z; ov.w = xv.w - rv.w;
        o4[i] = ov;
    }
    if (write_extra && blockIdx.x == 0 && threadIdx.x < Q_)
        out[OUT_LOSS_OFF + threadIdx.x] =
            g_loss[threadIdx.x] * (1.0f / ((float)M_ * (float)D_));
}

// ---------------------------------------------------------------------------
extern "C" void kernel_launch(void* const* d_in, const int* in_sizes, int n_in,
                              void* d_out, int out_size) {
    const float* x   = (const float*)d_in[0];
    const float* cbs = (const float*)d_in[1];
    float* out = (float*)d_out;

    const int full = (int)(OUT_LOSS_OFF + Q_);
    const int write_extra = (out_size >= full) ? 1 : 0;
    float* idx_out = write_extra ? out + OUT_IDX_OFF : nullptr;

    static int attr_done = 0;
    if (!attr_done) {
        cudaFuncSetAttribute(screen_kernel,
                             cudaFuncAttributeMaxDynamicSharedMemorySize,
                             SMEM_BYTES);
        attr_done = 1;
    }

    init_kernel<<<1024, 256>>>(x);
    prep_kernel<<<(Q_ * C_ * 32) / 256, 256>>>(cbs);
    for (int q = 0; q < Q_; q++) {
        screen_kernel<<<dim3(64, 8), 256, SMEM_BYTES>>>(q);
        rerank_kernel<<<M_ / 8, 256>>>(cbs, idx_out, q, q == Q_ - 1);
    }
    final_kernel<<<512, 256>>>((const float4*)x, out, write_extra);
}